// round 3
// baseline (speedup 1.0000x reference)
#include <cuda_runtime.h>
#include <cuda_bf16.h>
#include <cstdint>
#include <cstddef>

#define B_   8
#define C_   512
#define L_   8192
#define NW   6
#define WELEM (512*512*3)
#define ACT  (B_*C_*L_)   // 33554432

// ---------------- scratch (device globals; no allocs allowed) ----------------
__device__ __align__(256) double         g_partial[NW*96];
__device__ __align__(256) float          g_scales[NW];
__device__ __align__(256) __nv_bfloat16  g_wq[NW*WELEM];    // per weight: [k][o][i] ternary
__device__ __align__(256) __nv_bfloat162 g_xp0[ACT];        // activation pairs (hi,lo) ping
__device__ __align__(256) __nv_bfloat162 g_xp1[ACT];        // activation pairs pong
__device__ __align__(256) __nv_bfloat162 g_yp[ACT];         // branch intermediate pairs
__device__ __align__(256) float          g_xf0[ACT];        // fp32 residual ping
__device__ __align__(256) float          g_xf1[ACT];        // fp32 residual pong

struct WPtrs { const float* p[NW]; };

// ---------------- pass 1: deterministic |w| partial sums (double) ------------
__global__ void wabs_kernel(WPtrs wp) {
    int e = blockIdx.y;
    int chunk = blockIdx.x;                 // 96 chunks of 8192
    const float* w = wp.p[e] + chunk * 8192;
    double s = 0.0;
    for (int i = threadIdx.x; i < 8192; i += 256) s += (double)fabsf(w[i]);
    __shared__ double sm[256];
    sm[threadIdx.x] = s;
    __syncthreads();
    for (int off = 128; off > 0; off >>= 1) {
        if (threadIdx.x < off) sm[threadIdx.x] += sm[threadIdx.x + off];
        __syncthreads();
    }
    if (threadIdx.x == 0) g_partial[e*96 + chunk] = sm[0];
}

// ---------------- pass 2: finalize scales ------------------------------------
__global__ void finalize_kernel() {
    int e = threadIdx.x;
    if (e < NW) {
        double s = 0.0;
        for (int i = 0; i < 96; i++) s += g_partial[e*96 + i];
        g_scales[e] = (float)(s / (double)WELEM) + 1e-5f;
    }
}

// ---------------- pass 3: ternary quantize + rearrange [o][i][k]->[k][o][i] --
__global__ void quant_kernel(WPtrs wp) {
    int idx = blockIdx.x * 256 + threadIdx.x;
    if (idx >= NW * WELEM) return;
    int e = idx / WELEM;
    int r = idx - e * WELEM;
    int o = r / 1536;
    int rem = r - o * 1536;
    int i = rem / 3;
    int k = rem - i * 3;
    float sc = g_scales[e];
    float t = rintf(wp.p[e][r] / sc);       // round-half-even, matches jnp.round
    t = fminf(1.f, fmaxf(-1.f, t));
    g_wq[(size_t)e * WELEM + ((size_t)(k * C_ + o) * C_ + i)] = __float2bfloat16(t);
}

// ---------------- x -> (hi,lo) bf16 pair -------------------------------------
__device__ __forceinline__ __nv_bfloat162 split_pair(float v) {
    __nv_bfloat16 hi = __float2bfloat16(v);
    __nv_bfloat16 lo = __float2bfloat16(v - __bfloat162float(hi));
    __nv_bfloat162 p; p.x = hi; p.y = lo;
    return p;
}

__global__ void xcvt_kernel(const float* __restrict__ x) {
    int idx = blockIdx.x * 256 + threadIdx.x;
    if (idx < ACT) g_xp0[idx] = split_pair(x[idx]);
}

// ---------------- fused conv (GEMM via mma.sync bf16, hi/lo exact input) ------
// MODE 0: out_p = pair( leaky( scale*acc + bias ) )           (conv A)
// MODE 1: r = prev_f + scale*acc + bias; out_f = r; opt out_p (conv B + residual)
template<int D, int MODE>
__global__ __launch_bounds__(256, 2)
void conv_kernel(const __nv_bfloat162* __restrict__ xin,    // pairs [C][L]
                 const __nv_bfloat16* __restrict__ wq,      // [3][512][512] ternary bf16
                 const float* __restrict__ scale_p,
                 const float* __restrict__ bias,
                 const float* __restrict__ prev_f,
                 float* __restrict__ out_f,
                 __nv_bfloat162* __restrict__ out_p,
                 int write_p)
{
    constexpr int NR = 128 + 2*D;   // x rows incl. halo
    constexpr int KP = 24;          // padded k-width: 12-word rows -> conflict-free frag LDS
    __shared__ __nv_bfloat16 Ws[3][128][KP];   // [tap][o][i]
    __shared__ __nv_bfloat16 Xs[2][NR][KP];    // [plane][n+halo][i]  (transposed)

    const int n0 = blockIdx.x * 128;
    const int o0 = blockIdx.y * 128;
    const int b  = blockIdx.z;
    const int tid  = threadIdx.x;
    const int lane = tid & 31;
    const int wid  = tid >> 5;
    const int oW = (wid & 3) * 32;   // warp o-offset
    const int nW = (wid >> 2) * 64;  // warp n-offset

    float acc[2][8][4];
#pragma unroll
    for (int a = 0; a < 2; a++)
#pragma unroll
        for (int c = 0; c < 8; c++)
#pragma unroll
            for (int j = 0; j < 4; j++) acc[a][c][j] = 0.f;

    const __nv_bfloat162* xb = xin + (size_t)b * C_ * L_;

    for (int ic = 0; ic < C_; ic += 16) {
        __syncthreads();
        // weights: 3 taps x 128 rows x 16 i (32B per row, vectorized)
        for (int r = tid; r < 384; r += 256) {
            int k = r >> 7, o = r & 127;
            const uint4* src = (const uint4*)(wq + ((size_t)(k * C_ + o0 + o) * C_ + ic));
            uint4 v0 = src[0], v1 = src[1];
            *((uint4*)&Ws[k][o][0]) = v0;
            *((uint4*)&Ws[k][o][8]) = v1;
        }
        // x tile (transposed store, hi/lo planes), zero-padded at boundary
        for (int idx = tid; idx < 16 * NR; idx += 256) {
            int il = idx / NR;
            int r  = idx - il * NR;
            int l  = n0 - D + r;
            __nv_bfloat162 v;
            v.x = __float2bfloat16(0.f); v.y = v.x;
            if (l >= 0 && l < L_) v = xb[(size_t)(ic + il) * L_ + l];
            Xs[0][r][il] = v.x;
            Xs[1][r][il] = v.y;
        }
        __syncthreads();

#pragma unroll
        for (int t = 0; t < 3; t++) {
            uint32_t af[2][4];
#pragma unroll
            for (int mi = 0; mi < 2; mi++) {
                int ro = oW + mi*16 + (lane >> 2);
                int co = (lane & 3) * 2;
                af[mi][0] = *(const uint32_t*)&Ws[t][ro    ][co    ];
                af[mi][1] = *(const uint32_t*)&Ws[t][ro + 8][co    ];
                af[mi][2] = *(const uint32_t*)&Ws[t][ro    ][co + 8];
                af[mi][3] = *(const uint32_t*)&Ws[t][ro + 8][co + 8];
            }
#pragma unroll
            for (int p = 0; p < 2; p++) {
                uint32_t bf[8][2];
#pragma unroll
                for (int ni = 0; ni < 8; ni++) {
                    int rn = nW + ni*8 + (lane >> 2) + t * D;
                    int ck = (lane & 3) * 2;
                    bf[ni][0] = *(const uint32_t*)&Xs[p][rn][ck    ];
                    bf[ni][1] = *(const uint32_t*)&Xs[p][rn][ck + 8];
                }
#pragma unroll
                for (int mi = 0; mi < 2; mi++)
#pragma unroll
                    for (int ni = 0; ni < 8; ni++) {
                        asm volatile(
                            "mma.sync.aligned.m16n8k16.row.col.f32.bf16.bf16.f32 "
                            "{%0,%1,%2,%3}, {%4,%5,%6,%7}, {%8,%9}, {%0,%1,%2,%3};\n"
                            : "+f"(acc[mi][ni][0]), "+f"(acc[mi][ni][1]),
                              "+f"(acc[mi][ni][2]), "+f"(acc[mi][ni][3])
                            : "r"(af[mi][0]), "r"(af[mi][1]), "r"(af[mi][2]), "r"(af[mi][3]),
                              "r"(bf[ni][0]), "r"(bf[ni][1]));
                    }
            }
        }
    }

    const float scale = *scale_p;
#pragma unroll
    for (int mi = 0; mi < 2; mi++) {
#pragma unroll
        for (int half = 0; half < 2; half++) {
            int o = o0 + oW + mi*16 + (lane >> 2) + half*8;
            float bv = bias[o];
#pragma unroll
            for (int ni = 0; ni < 8; ni++) {
                int c = n0 + nW + ni*8 + (lane & 3)*2;
                float v0 = acc[mi][ni][half*2 + 0] * scale + bv;
                float v1 = acc[mi][ni][half*2 + 1] * scale + bv;
                size_t gi = ((size_t)b * C_ + o) * L_ + c;
                if (MODE == 0) {
                    v0 = v0 >= 0.f ? v0 : 0.1f * v0;
                    v1 = v1 >= 0.f ? v1 : 0.1f * v1;
                    __nv_bfloat162 p0 = split_pair(v0);
                    __nv_bfloat162 p1 = split_pair(v1);
                    uint2 st;
                    st.x = *(const uint32_t*)&p0;
                    st.y = *(const uint32_t*)&p1;
                    *((uint2*)(out_p + gi)) = st;
                } else {
                    float2 pv = *((const float2*)(prev_f + gi));
                    float r0 = pv.x + v0, r1 = pv.y + v1;
                    *((float2*)(out_f + gi)) = make_float2(r0, r1);
                    if (write_p) {
                        __nv_bfloat162 p0 = split_pair(r0);
                        __nv_bfloat162 p1 = split_pair(r1);
                        uint2 st;
                        st.x = *(const uint32_t*)&p0;
                        st.y = *(const uint32_t*)&p1;
                        *((uint2*)(out_p + gi)) = st;
                    }
                }
            }
        }
    }
}

// ---------------- launch ------------------------------------------------------
extern "C" void kernel_launch(void* const* d_in, const int* in_sizes, int n_in,
                              void* d_out, int out_size)
{
    (void)in_sizes; (void)n_in; (void)out_size;
    const float* x = (const float*)d_in[0];
    WPtrs wp;
    const float* biasA[3];
    const float* biasB[3];
    for (int br = 0; br < 3; br++) {
        wp.p[2*br + 0] = (const float*)d_in[1 + 4*br];   // wA
        biasA[br]      = (const float*)d_in[2 + 4*br];   // bA
        wp.p[2*br + 1] = (const float*)d_in[3 + 4*br];   // wB
        biasB[br]      = (const float*)d_in[4 + 4*br];   // bB
    }

    void *p_wq, *p_x0, *p_x1, *p_y, *p_f0, *p_f1, *p_sc;
    cudaGetSymbolAddress(&p_wq, g_wq);
    cudaGetSymbolAddress(&p_x0, g_xp0);
    cudaGetSymbolAddress(&p_x1, g_xp1);
    cudaGetSymbolAddress(&p_y,  g_yp);
    cudaGetSymbolAddress(&p_f0, g_xf0);
    cudaGetSymbolAddress(&p_f1, g_xf1);
    cudaGetSymbolAddress(&p_sc, g_scales);
    __nv_bfloat16*  wq  = (__nv_bfloat16*)p_wq;
    __nv_bfloat162* xp0 = (__nv_bfloat162*)p_x0;
    __nv_bfloat162* xp1 = (__nv_bfloat162*)p_x1;
    __nv_bfloat162* yp  = (__nv_bfloat162*)p_y;
    float* xf0 = (float*)p_f0;
    float* xf1 = (float*)p_f1;
    float* scales = (float*)p_sc;

    dim3 rg(96, NW);
    wabs_kernel<<<rg, 256>>>(wp);
    finalize_kernel<<<1, 32>>>();
    quant_kernel<<<(NW * WELEM + 255) / 256, 256>>>(wp);
    xcvt_kernel<<<(ACT + 255) / 256, 256>>>(x);

    dim3 cg(L_ / 128, C_ / 128, B_);
    // branch 0: dilation 1
    conv_kernel<1, 0><<<cg, 256>>>(xp0, wq + 0*(size_t)WELEM, scales + 0, biasA[0],
                                   nullptr, nullptr, yp, 0);
    conv_kernel<1, 1><<<cg, 256>>>(yp,  wq + 1*(size_t)WELEM, scales + 1, biasB[0],
                                   x, xf0, xp1, 1);
    // branch 1: dilation 3
    conv_kernel<3, 0><<<cg, 256>>>(xp1, wq + 2*(size_t)WELEM, scales + 2, biasA[1],
                                   nullptr, nullptr, yp, 0);
    conv_kernel<1, 1><<<cg, 256>>>(yp,  wq + 3*(size_t)WELEM, scales + 3, biasB[1],
                                   xf0, xf1, xp0, 1);
    // branch 2: dilation 5
    conv_kernel<5, 0><<<cg, 256>>>(xp0, wq + 4*(size_t)WELEM, scales + 4, biasA[2],
                                   nullptr, nullptr, yp, 0);
    conv_kernel<1, 1><<<cg, 256>>>(yp,  wq + 5*(size_t)WELEM, scales + 5, biasB[2],
                                   xf1, (float*)d_out, nullptr, 0);
}

// round 4
// speedup vs baseline: 1.3103x; 1.3103x over previous
#include <cuda_runtime.h>
#include <cuda_bf16.h>
#include <cuda_fp16.h>
#include <cstdint>
#include <cstddef>

#define B_   8
#define C_   512
#define L_   8192
#define NW   6
#define WELEM (512*512*3)
#define ACT  (B_*C_*L_)   // 33554432

// ---------------- scratch (device globals; no allocs allowed) ----------------
__device__ __align__(256) double  g_partial[NW*96];
__device__ __align__(256) float   g_scales[NW];
__device__ __align__(256) __half  g_wq[NW*WELEM];   // per weight: [k][o][i] ternary fp16
__device__ __align__(256) __half  g_xh0[ACT];       // fp16 activation ping
__device__ __align__(256) __half  g_xh1[ACT];       // fp16 activation pong
__device__ __align__(256) __half  g_yh[ACT];        // fp16 branch intermediate
__device__ __align__(256) float   g_xf0[ACT];       // fp32 residual ping
__device__ __align__(256) float   g_xf1[ACT];       // fp32 residual pong

struct WPtrs { const float* p[NW]; };

// ---------------- pass 1: deterministic |w| partial sums (double) ------------
__global__ void wabs_kernel(WPtrs wp) {
    int e = blockIdx.y;
    int chunk = blockIdx.x;                 // 96 chunks of 8192
    const float* w = wp.p[e] + chunk * 8192;
    double s = 0.0;
    for (int i = threadIdx.x; i < 8192; i += 256) s += (double)fabsf(w[i]);
    __shared__ double sm[256];
    sm[threadIdx.x] = s;
    __syncthreads();
    for (int off = 128; off > 0; off >>= 1) {
        if (threadIdx.x < off) sm[threadIdx.x] += sm[threadIdx.x + off];
        __syncthreads();
    }
    if (threadIdx.x == 0) g_partial[e*96 + chunk] = sm[0];
}

// ---------------- pass 2: finalize scales ------------------------------------
__global__ void finalize_kernel() {
    int e = threadIdx.x;
    if (e < NW) {
        double s = 0.0;
        for (int i = 0; i < 96; i++) s += g_partial[e*96 + i];
        g_scales[e] = (float)(s / (double)WELEM) + 1e-5f;
    }
}

// ---------------- pass 3: ternary quantize + rearrange [o][i][k]->[k][o][i] --
__global__ void quant_kernel(WPtrs wp) {
    int idx = blockIdx.x * 256 + threadIdx.x;
    if (idx >= NW * WELEM) return;
    int e = idx / WELEM;
    int r = idx - e * WELEM;
    int o = r / 1536;
    int rem = r - o * 1536;
    int i = rem / 3;
    int k = rem - i * 3;
    float sc = g_scales[e];
    float t = rintf(wp.p[e][r] / sc);       // round-half-even, matches jnp.round
    t = fminf(1.f, fmaxf(-1.f, t));
    g_wq[(size_t)e * WELEM + ((size_t)(k * C_ + o) * C_ + i)] = __float2half_rn(t);
}

// ---------------- x -> fp16 ---------------------------------------------------
__global__ void xcvt_kernel(const float* __restrict__ x) {
    int idx = (blockIdx.x * 256 + threadIdx.x) * 2;
    if (idx < ACT) {
        float2 v = *(const float2*)(x + idx);
        __half2 h; h.x = __float2half_rn(v.x); h.y = __float2half_rn(v.y);
        *(__half2*)(g_xh0 + idx) = h;
    }
}

// ---------------- fused conv (GEMM via mma.sync fp16) -------------------------
// MODE 0: out_h = fp16( leaky( scale*acc + bias ) )            (conv A)
// MODE 1: r = prev_f + scale*acc + bias; out_f = r; opt out_h  (conv B + residual)
template<int D, int MODE>
__global__ __launch_bounds__(256, 2)
void conv_kernel(const __half* __restrict__ xin,        // [C][L] fp16
                 const __half* __restrict__ wq,         // [3][512][512] ternary fp16
                 const float* __restrict__ scale_p,
                 const float* __restrict__ bias,
                 const float* __restrict__ prev_f,
                 float* __restrict__ out_f,
                 __half* __restrict__ out_h,
                 int write_h)
{
    constexpr int NR = 128 + 2*D;   // x rows incl. halo
    constexpr int KP = 24;          // padded k-width: 12-word rows -> conflict-free frag LDS
    __shared__ __half Ws[3][128][KP];   // [tap][o][i]
    __shared__ __half Xs[NR][KP];       // [n+halo][i]  (transposed)

    const int n0 = blockIdx.x * 128;
    const int o0 = blockIdx.y * 128;
    const int b  = blockIdx.z;
    const int tid  = threadIdx.x;
    const int lane = tid & 31;
    const int wid  = tid >> 5;
    const int oW = (wid & 3) * 32;   // warp o-offset
    const int nW = (wid >> 2) * 64;  // warp n-offset

    float acc[2][8][4];
#pragma unroll
    for (int a = 0; a < 2; a++)
#pragma unroll
        for (int c = 0; c < 8; c++)
#pragma unroll
            for (int j = 0; j < 4; j++) acc[a][c][j] = 0.f;

    const __half* xb = xin + (size_t)b * C_ * L_;
    const __half z16 = __float2half_rn(0.f);

    for (int ic = 0; ic < C_; ic += 16) {
        __syncthreads();
        // weights: 3 taps x 128 rows x 16 i (32B per row, vectorized)
        for (int r = tid; r < 384; r += 256) {
            int k = r >> 7, o = r & 127;
            const uint4* src = (const uint4*)(wq + ((size_t)(k * C_ + o0 + o) * C_ + ic));
            uint4 v0 = src[0], v1 = src[1];
            *((uint4*)&Ws[k][o][0]) = v0;
            *((uint4*)&Ws[k][o][8]) = v1;
        }
        // x tile (transposed store), zero-padded at sequence boundary
        for (int idx = tid; idx < 16 * NR; idx += 256) {
            int il = idx / NR;
            int r  = idx - il * NR;
            int l  = n0 - D + r;
            __half v = z16;
            if (l >= 0 && l < L_) v = xb[(size_t)(ic + il) * L_ + l];
            Xs[r][il] = v;
        }
        __syncthreads();

#pragma unroll
        for (int t = 0; t < 3; t++) {
            uint32_t af[2][4];
#pragma unroll
            for (int mi = 0; mi < 2; mi++) {
                int ro = oW + mi*16 + (lane >> 2);
                int co = (lane & 3) * 2;
                af[mi][0] = *(const uint32_t*)&Ws[t][ro    ][co    ];
                af[mi][1] = *(const uint32_t*)&Ws[t][ro + 8][co    ];
                af[mi][2] = *(const uint32_t*)&Ws[t][ro    ][co + 8];
                af[mi][3] = *(const uint32_t*)&Ws[t][ro + 8][co + 8];
            }
            uint32_t bf[8][2];
#pragma unroll
            for (int ni = 0; ni < 8; ni++) {
                int rn = nW + ni*8 + (lane >> 2) + t * D;
                int ck = (lane & 3) * 2;
                bf[ni][0] = *(const uint32_t*)&Xs[rn][ck    ];
                bf[ni][1] = *(const uint32_t*)&Xs[rn][ck + 8];
            }
#pragma unroll
            for (int mi = 0; mi < 2; mi++)
#pragma unroll
                for (int ni = 0; ni < 8; ni++) {
                    asm volatile(
                        "mma.sync.aligned.m16n8k16.row.col.f32.f16.f16.f32 "
                        "{%0,%1,%2,%3}, {%4,%5,%6,%7}, {%8,%9}, {%0,%1,%2,%3};\n"
                        : "+f"(acc[mi][ni][0]), "+f"(acc[mi][ni][1]),
                          "+f"(acc[mi][ni][2]), "+f"(acc[mi][ni][3])
                        : "r"(af[mi][0]), "r"(af[mi][1]), "r"(af[mi][2]), "r"(af[mi][3]),
                          "r"(bf[ni][0]), "r"(bf[ni][1]));
                }
        }
    }

    const float scale = *scale_p;
#pragma unroll
    for (int mi = 0; mi < 2; mi++) {
#pragma unroll
        for (int half = 0; half < 2; half++) {
            int o = o0 + oW + mi*16 + (lane >> 2) + half*8;
            float bv = bias[o];
#pragma unroll
            for (int ni = 0; ni < 8; ni++) {
                int c = n0 + nW + ni*8 + (lane & 3)*2;
                float v0 = acc[mi][ni][half*2 + 0] * scale + bv;
                float v1 = acc[mi][ni][half*2 + 1] * scale + bv;
                size_t gi = ((size_t)b * C_ + o) * L_ + c;
                if (MODE == 0) {
                    v0 = v0 >= 0.f ? v0 : 0.1f * v0;
                    v1 = v1 >= 0.f ? v1 : 0.1f * v1;
                    __half2 h2;
                    h2.x = __float2half_rn(v0);
                    h2.y = __float2half_rn(v1);
                    *((__half2*)(out_h + gi)) = h2;
                } else {
                    float2 pv = *((const float2*)(prev_f + gi));
                    float r0 = pv.x + v0, r1 = pv.y + v1;
                    *((float2*)(out_f + gi)) = make_float2(r0, r1);
                    if (write_h) {
                        __half2 h2;
                        h2.x = __float2half_rn(r0);
                        h2.y = __float2half_rn(r1);
                        *((__half2*)(out_h + gi)) = h2;
                    }
                }
            }
        }
    }
}

// ---------------- launch ------------------------------------------------------
extern "C" void kernel_launch(void* const* d_in, const int* in_sizes, int n_in,
                              void* d_out, int out_size)
{
    (void)in_sizes; (void)n_in; (void)out_size;
    const float* x = (const float*)d_in[0];
    WPtrs wp;
    const float* biasA[3];
    const float* biasB[3];
    for (int br = 0; br < 3; br++) {
        wp.p[2*br + 0] = (const float*)d_in[1 + 4*br];   // wA
        biasA[br]      = (const float*)d_in[2 + 4*br];   // bA
        wp.p[2*br + 1] = (const float*)d_in[3 + 4*br];   // wB
        biasB[br]      = (const float*)d_in[4 + 4*br];   // bB
    }

    void *p_wq, *p_x0, *p_x1, *p_y, *p_f0, *p_f1, *p_sc;
    cudaGetSymbolAddress(&p_wq, g_wq);
    cudaGetSymbolAddress(&p_x0, g_xh0);
    cudaGetSymbolAddress(&p_x1, g_xh1);
    cudaGetSymbolAddress(&p_y,  g_yh);
    cudaGetSymbolAddress(&p_f0, g_xf0);
    cudaGetSymbolAddress(&p_f1, g_xf1);
    cudaGetSymbolAddress(&p_sc, g_scales);
    __half* wq  = (__half*)p_wq;
    __half* xh0 = (__half*)p_x0;
    __half* xh1 = (__half*)p_x1;
    __half* yh  = (__half*)p_y;
    float* xf0 = (float*)p_f0;
    float* xf1 = (float*)p_f1;
    float* scales = (float*)p_sc;

    dim3 rg(96, NW);
    wabs_kernel<<<rg, 256>>>(wp);
    finalize_kernel<<<1, 32>>>();
    quant_kernel<<<(NW * WELEM + 255) / 256, 256>>>(wp);
    xcvt_kernel<<<(ACT/2 + 255) / 256, 256>>>(x);

    dim3 cg(L_ / 128, C_ / 128, B_);
    // branch 0: dilation 1
    conv_kernel<1, 0><<<cg, 256>>>(xh0, wq + 0*(size_t)WELEM, scales + 0, biasA[0],
                                   nullptr, nullptr, yh, 0);
    conv_kernel<1, 1><<<cg, 256>>>(yh,  wq + 1*(size_t)WELEM, scales + 1, biasB[0],
                                   x, xf0, xh1, 1);
    // branch 1: dilation 3
    conv_kernel<3, 0><<<cg, 256>>>(xh1, wq + 2*(size_t)WELEM, scales + 2, biasA[1],
                                   nullptr, nullptr, yh, 0);
    conv_kernel<1, 1><<<cg, 256>>>(yh,  wq + 3*(size_t)WELEM, scales + 3, biasB[1],
                                   xf0, xf1, xh0, 1);
    // branch 2: dilation 5
    conv_kernel<5, 0><<<cg, 256>>>(xh0, wq + 4*(size_t)WELEM, scales + 4, biasA[2],
                                   nullptr, nullptr, yh, 0);
    conv_kernel<1, 1><<<cg, 256>>>(yh,  wq + 5*(size_t)WELEM, scales + 5, biasB[2],
                                   xf1, (float*)d_out, nullptr, 0);
}

// round 6
// speedup vs baseline: 1.8488x; 1.4110x over previous
#include <cuda_runtime.h>
#include <cuda_fp16.h>
#include <cstdint>
#include <cstddef>

#define B_   8
#define C_   512
#define L_   8192
#define NW   6
#define WELEM (512*512*3)
#define ACT  (B_*C_*L_)   // 33554432

// ---------------- scratch (device globals; no allocs allowed) ----------------
__device__ __align__(256) double  g_partial[NW*96];
__device__ __align__(256) float   g_scales[NW];
__device__ __align__(256) __half  g_wq[NW*WELEM];   // per weight: [k][o][i] ternary fp16
__device__ __align__(256) __half  g_xt0[ACT];       // fp16 activations [b][L][C] ping
__device__ __align__(256) __half  g_xt1[ACT];       // pong
__device__ __align__(256) __half  g_yt[ACT];        // branch intermediate [b][L][C]
__device__ __align__(256) float   g_xf0[ACT];       // fp32 residual [b][C][L] ping
__device__ __align__(256) float   g_xf1[ACT];       // pong

struct WPtrs { const float* p[NW]; };

__device__ __forceinline__ uint32_t smem_u32(const void* p) {
    uint32_t a;
    asm("{ .reg .u64 t; cvta.to.shared.u64 t, %1; cvt.u32.u64 %0, t; }"
        : "=r"(a) : "l"(p));
    return a;
}
__device__ __forceinline__ void cpa16(uint32_t dst, const void* src, uint32_t ssize) {
    asm volatile("cp.async.cg.shared.global [%0], [%1], 16, %2;"
                 :: "r"(dst), "l"(src), "r"(ssize) : "memory");
}

// ---------------- pass 1: deterministic |w| partial sums (double) ------------
__global__ void wabs_kernel(WPtrs wp) {
    int e = blockIdx.y;
    int chunk = blockIdx.x;                 // 96 chunks of 8192
    const float* w = wp.p[e] + chunk * 8192;
    double s = 0.0;
    for (int i = threadIdx.x; i < 8192; i += 256) s += (double)fabsf(w[i]);
    __shared__ double sm[256];
    sm[threadIdx.x] = s;
    __syncthreads();
    for (int off = 128; off > 0; off >>= 1) {
        if (threadIdx.x < off) sm[threadIdx.x] += sm[threadIdx.x + off];
        __syncthreads();
    }
    if (threadIdx.x == 0) g_partial[e*96 + chunk] = sm[0];
}

// ---------------- pass 2: finalize scales ------------------------------------
__global__ void finalize_kernel() {
    int e = threadIdx.x;
    if (e < NW) {
        double s = 0.0;
        for (int i = 0; i < 96; i++) s += g_partial[e*96 + i];
        g_scales[e] = (float)(s / (double)WELEM) + 1e-5f;
    }
}

// ---------------- pass 3: ternary quantize + rearrange [o][i][k]->[k][o][i] --
__global__ void quant_kernel(WPtrs wp) {
    int idx = blockIdx.x * 256 + threadIdx.x;
    if (idx >= NW * WELEM) return;
    int e = idx / WELEM;
    int r = idx - e * WELEM;
    int o = r / 1536;
    int rem = r - o * 1536;
    int i = rem / 3;
    int k = rem - i * 3;
    float sc = g_scales[e];
    float t = rintf(wp.p[e][r] / sc);       // round-half-even, matches jnp.round
    t = fminf(1.f, fmaxf(-1.f, t));
    g_wq[(size_t)e * WELEM + ((size_t)(k * C_ + o) * C_ + i)] = __float2half_rn(t);
}

// ---------------- transpose x[b][C][L] fp32 -> xT[b][L][C] fp16 ---------------
__global__ void tr_kernel(const float* __restrict__ x) {
    __shared__ __half t[32][33];
    int b  = blockIdx.z;
    int l0 = blockIdx.x * 32, c0 = blockIdx.y * 32;
    int tx = threadIdx.x, ty = threadIdx.y;   // 32 x 8
    const float* xp = x + ((size_t)b * C_ + c0) * L_ + l0;
#pragma unroll
    for (int j = 0; j < 32; j += 8)
        t[ty + j][tx] = __float2half_rn(xp[(size_t)(ty + j) * L_ + tx]);
    __syncthreads();
    __half* xo = g_xt0 + ((size_t)b * L_ + l0) * C_ + c0;
#pragma unroll
    for (int j = 0; j < 32; j += 8)
        xo[(size_t)(ty + j) * C_ + tx] = t[tx][ty + j];
}

// ---------------- fused conv (mma.sync fp16, cp.async double-buffered) --------
// A = weights [3][512o][512i], B = activations xT [b][L][C].
// CTA tile: 128 o x 128 n, K = 3 taps x 512 ic in 32 chunks of 16.
// Xs rows span l in [n0-8, n0+136): covers halo for D<=5, rows cp.async'd
// directly from [L][C] layout (per-row src-size=0 gives exact zero padding).
// MODE 0: out_h[L][C] = fp16(leaky(scale*acc + bias))
// MODE 1: r = prev_f + scale*acc + bias -> out_f [C][L] fp32; opt out_h [L][C]
template<int D, int MODE>
__global__ __launch_bounds__(256, 2)
void conv_kernel(const __half* __restrict__ xin,        // [b][L][C] fp16
                 const __half* __restrict__ wq,         // [3][512][512] ternary fp16
                 const float* __restrict__ scale_p,
                 const float* __restrict__ bias,
                 const float* __restrict__ prev_f,
                 float* __restrict__ out_f,
                 __half* __restrict__ out_h,
                 int write_h)
{
    constexpr int NR = 144;          // 128 + 16 halo rows (origin n0-8)
    constexpr int KP = 24;           // padded X row: 48B -> conflict-free B-frag LDS
    __shared__ __half Ws[2][3][128][16];   // 2 x 12KB
    __shared__ __half Xs[2][NR][KP];       // 2 x 6.75KB

    const int n0 = blockIdx.x * 128;
    const int o0 = blockIdx.y * 128;
    const int b  = blockIdx.z;
    const int tid  = threadIdx.x;
    const int lane = tid & 31;
    const int wid  = tid >> 5;
    const int oW = (wid & 3) * 32;   // warp o-offset
    const int nW = (wid >> 2) * 64;  // warp n-offset

    float acc[2][8][4];
#pragma unroll
    for (int a = 0; a < 2; a++)
#pragma unroll
        for (int c = 0; c < 8; c++)
#pragma unroll
            for (int j = 0; j < 4; j++) acc[a][c][j] = 0.f;

    const size_t bL = (size_t)b * L_;

    auto fill = [&](int s, int buf) {
        int ic = s * 16;
        // weights: 3 taps x 128 rows x 16 i (2 x 16B per row)
        for (int r = tid; r < 384; r += 256) {
            int k = r >> 7, o = r & 127;
            const __half* src = wq + ((size_t)(k * C_ + o0 + o)) * C_ + ic;
            uint32_t dst = smem_u32(&Ws[buf][k][o][0]);
            cpa16(dst,      src,     16);
            cpa16(dst + 16, src + 8, 16);
        }
        // x: NR rows x 16 ch (2 x 16B per row), zero-fill out-of-range rows
        for (int t2 = tid; t2 < 2 * NR; t2 += 256) {
            int r = t2 >> 1, h = t2 & 1;
            int l = n0 - 8 + r;
            int lc = l < 0 ? 0 : (l >= L_ ? L_ - 1 : l);
            uint32_t sz = (l >= 0 && l < L_) ? 16u : 0u;
            const __half* src = xin + (bL + lc) * C_ + ic + h * 8;
            cpa16(smem_u32(&Xs[buf][r][h * 8]), src, sz);
        }
        asm volatile("cp.async.commit_group;" ::: "memory");
    };

    fill(0, 0);
    for (int s = 0; s < 32; s++) {
        const int buf = s & 1;
        asm volatile("cp.async.wait_group 0;" ::: "memory");
        __syncthreads();                       // buf data visible; prev readers done
        if (s + 1 < 32) fill(s + 1, buf ^ 1);  // overlaps compute below

#pragma unroll
        for (int t = 0; t < 3; t++) {
            uint32_t af[2][4];
#pragma unroll
            for (int mi = 0; mi < 2; mi++) {
                int ro = oW + mi*16 + (lane >> 2);
                int co = (lane & 3) * 2;
                af[mi][0] = *(const uint32_t*)&Ws[buf][t][ro    ][co    ];
                af[mi][1] = *(const uint32_t*)&Ws[buf][t][ro + 8][co    ];
                af[mi][2] = *(const uint32_t*)&Ws[buf][t][ro    ][co + 8];
                af[mi][3] = *(const uint32_t*)&Ws[buf][t][ro + 8][co + 8];
            }
            uint32_t bf[8][2];
#pragma unroll
            for (int ni = 0; ni < 8; ni++) {
                int rn = nW + ni*8 + (lane >> 2) + (8 - D) + t * D;
                int ck = (lane & 3) * 2;
                bf[ni][0] = *(const uint32_t*)&Xs[buf][rn][ck    ];
                bf[ni][1] = *(const uint32_t*)&Xs[buf][rn][ck + 8];
            }
#pragma unroll
            for (int mi = 0; mi < 2; mi++)
#pragma unroll
                for (int ni = 0; ni < 8; ni++) {
                    asm volatile(
                        "mma.sync.aligned.m16n8k16.row.col.f32.f16.f16.f32 "
                        "{%0,%1,%2,%3}, {%4,%5,%6,%7}, {%8,%9}, {%0,%1,%2,%3};\n"
                        : "+f"(acc[mi][ni][0]), "+f"(acc[mi][ni][1]),
                          "+f"(acc[mi][ni][2]), "+f"(acc[mi][ni][3])
                        : "r"(af[mi][0]), "r"(af[mi][1]), "r"(af[mi][2]), "r"(af[mi][3]),
                          "r"(bf[ni][0]), "r"(bf[ni][1]));
                }
        }
    }

    const float scale = *scale_p;
#pragma unroll
    for (int mi = 0; mi < 2; mi++) {
#pragma unroll
        for (int half = 0; half < 2; half++) {
            int o = o0 + oW + mi*16 + (lane >> 2) + half*8;
            float bv = bias[o];
#pragma unroll
            for (int ni = 0; ni < 8; ni++) {
                int c = n0 + nW + ni*8 + (lane & 3)*2;
                float v0 = acc[mi][ni][half*2 + 0] * scale + bv;
                float v1 = acc[mi][ni][half*2 + 1] * scale + bv;
                if (MODE == 0) {
                    v0 = v0 >= 0.f ? v0 : 0.1f * v0;
                    v1 = v1 >= 0.f ? v1 : 0.1f * v1;
                    out_h[(bL + c    ) * C_ + o] = __float2half_rn(v0);
                    out_h[(bL + c + 1) * C_ + o] = __float2half_rn(v1);
                } else {
                    size_t gi = ((size_t)b * C_ + o) * L_ + c;
                    float2 pv = *((const float2*)(prev_f + gi));
                    float r0 = pv.x + v0, r1 = pv.y + v1;
                    *((float2*)(out_f + gi)) = make_float2(r0, r1);
                    if (write_h) {
                        out_h[(bL + c    ) * C_ + o] = __float2half_rn(r0);
                        out_h[(bL + c + 1) * C_ + o] = __float2half_rn(r1);
                    }
                }
            }
        }
    }
}

// ---------------- launch ------------------------------------------------------
extern "C" void kernel_launch(void* const* d_in, const int* in_sizes, int n_in,
                              void* d_out, int out_size)
{
    (void)in_sizes; (void)n_in; (void)out_size;
    const float* x = (const float*)d_in[0];
    WPtrs wp;
    const float* biasA[3];
    const float* biasB[3];
    for (int br = 0; br < 3; br++) {
        wp.p[2*br + 0] = (const float*)d_in[1 + 4*br];   // wA
        biasA[br]      = (const float*)d_in[2 + 4*br];   // bA
        wp.p[2*br + 1] = (const float*)d_in[3 + 4*br];   // wB
        biasB[br]      = (const float*)d_in[4 + 4*br];   // bB
    }

    void *p_wq, *p_x0, *p_x1, *p_y, *p_f0, *p_f1, *p_sc;
    cudaGetSymbolAddress(&p_wq, g_wq);
    cudaGetSymbolAddress(&p_x0, g_xt0);
    cudaGetSymbolAddress(&p_x1, g_xt1);
    cudaGetSymbolAddress(&p_y,  g_yt);
    cudaGetSymbolAddress(&p_f0, g_xf0);
    cudaGetSymbolAddress(&p_f1, g_xf1);
    cudaGetSymbolAddress(&p_sc, g_scales);
    __half* wq  = (__half*)p_wq;
    __half* xt0 = (__half*)p_x0;
    __half* xt1 = (__half*)p_x1;
    __half* yt  = (__half*)p_y;
    float* xf0 = (float*)p_f0;
    float* xf1 = (float*)p_f1;
    float* scales = (float*)p_sc;

    dim3 rg(96, NW);
    wabs_kernel<<<rg, 256>>>(wp);
    finalize_kernel<<<1, 32>>>();
    quant_kernel<<<(NW * WELEM + 255) / 256, 256>>>(wp);
    dim3 tg(L_ / 32, C_ / 32, B_);
    tr_kernel<<<tg, dim3(32, 8)>>>(x);

    dim3 cg(L_ / 128, C_ / 128, B_);   // 64 x 4 x 8 = 2048 CTAs
    // branch 0: dilation 1
    conv_kernel<1, 0><<<cg, 256>>>(xt0, wq + 0*(size_t)WELEM, scales + 0, biasA[0],
                                   nullptr, nullptr, yt, 0);
    conv_kernel<1, 1><<<cg, 256>>>(yt,  wq + 1*(size_t)WELEM, scales + 1, biasB[0],
                                   x, xf0, xt1, 1);
    // branch 1: dilation 3
    conv_kernel<3, 0><<<cg, 256>>>(xt1, wq + 2*(size_t)WELEM, scales + 2, biasA[1],
                                   nullptr, nullptr, yt, 0);
    conv_kernel<1, 1><<<cg, 256>>>(yt,  wq + 3*(size_t)WELEM, scales + 3, biasB[1],
                                   xf0, xf1, xt0, 1);
    // branch 2: dilation 5
    conv_kernel<5, 0><<<cg, 256>>>(xt0, wq + 4*(size_t)WELEM, scales + 4, biasA[2],
                                   nullptr, nullptr, yt, 0);
    conv_kernel<1, 1><<<cg, 256>>>(yt,  wq + 5*(size_t)WELEM, scales + 5, biasB[2],
                                   xf1, (float*)d_out, nullptr, 0);
}

// round 12
// speedup vs baseline: 2.6523x; 1.4346x over previous
#include <cuda_runtime.h>
#include <cuda_fp16.h>
#include <cstdint>
#include <cstddef>

#define B_   8
#define C_   512
#define L_   8192
#define NW   6
#define WELEM (512*512*3)
#define ACT  (B_*C_*L_)   // 33554432

// ---------------- scratch (device globals; no allocs allowed) ----------------
__device__ __align__(256) double  g_partial[NW*96];
__device__ __align__(256) float   g_scales[NW];
__device__ __align__(256) __half  g_wq[NW*WELEM];   // per weight: [k][o][i] ternary fp16
__device__ __align__(256) __half  g_xt0[ACT];       // fp16 activations [b][L][C] ping
__device__ __align__(256) __half  g_xt1[ACT];       // pong
__device__ __align__(256) __half  g_yt[ACT];        // branch intermediate [b][L][C]
__device__ __align__(256) float   g_xf0[ACT];       // fp32 residual [b][C][L] ping
__device__ __align__(256) float   g_xf1[ACT];       // pong

struct WPtrs { const float* p[NW]; };

__device__ __forceinline__ uint32_t smem_u32(const void* p) {
    uint32_t a;
    asm("{ .reg .u64 t; cvta.to.shared.u64 t, %1; cvt.u32.u64 %0, t; }"
        : "=r"(a) : "l"(p));
    return a;
}
__device__ __forceinline__ void cpa16(uint32_t dst, const void* src, uint32_t ssize) {
    asm volatile("cp.async.cg.shared.global [%0], [%1], 16, %2;"
                 :: "r"(dst), "l"(src), "r"(ssize) : "memory");
}
#define LDSM_X4(r0,r1,r2,r3,a) \
    asm volatile("ldmatrix.sync.aligned.m8n8.x4.shared.b16 {%0,%1,%2,%3}, [%4];" \
                 : "=r"(r0),"=r"(r1),"=r"(r2),"=r"(r3) : "r"(a))
#define MMA16816(acc, A0,A1,A2,A3, B0,B1) \
    asm volatile( \
        "mma.sync.aligned.m16n8k16.row.col.f32.f16.f16.f32 " \
        "{%0,%1,%2,%3}, {%4,%5,%6,%7}, {%8,%9}, {%0,%1,%2,%3};\n" \
        : "+f"((acc)[0]), "+f"((acc)[1]), "+f"((acc)[2]), "+f"((acc)[3]) \
        : "r"(A0), "r"(A1), "r"(A2), "r"(A3), "r"(B0), "r"(B1))

// ---------------- pass 1: deterministic |w| partial sums (double) ------------
__global__ void wabs_kernel(WPtrs wp) {
    int e = blockIdx.y;
    int chunk = blockIdx.x;                 // 96 chunks of 8192
    const float* w = wp.p[e] + chunk * 8192;
    double s = 0.0;
    for (int i = threadIdx.x; i < 8192; i += 256) s += (double)fabsf(w[i]);
    __shared__ double sm[256];
    sm[threadIdx.x] = s;
    __syncthreads();
    for (int off = 128; off > 0; off >>= 1) {
        if (threadIdx.x < off) sm[threadIdx.x] += sm[threadIdx.x + off];
        __syncthreads();
    }
    if (threadIdx.x == 0) g_partial[e*96 + chunk] = sm[0];
}

// ---------------- pass 2: finalize scales ------------------------------------
__global__ void finalize_kernel() {
    int e = threadIdx.x;
    if (e < NW) {
        double s = 0.0;
        for (int i = 0; i < 96; i++) s += g_partial[e*96 + i];
        g_scales[e] = (float)(s / (double)WELEM) + 1e-5f;
    }
}

// ---------------- pass 3: ternary quantize + rearrange [o][i][k]->[k][o][i] --
__global__ void quant_kernel(WPtrs wp) {
    int idx = blockIdx.x * 256 + threadIdx.x;
    if (idx >= NW * WELEM) return;
    int e = idx / WELEM;
    int r = idx - e * WELEM;
    int o = r / 1536;
    int rem = r - o * 1536;
    int i = rem / 3;
    int k = rem - i * 3;
    float sc = g_scales[e];
    float t = rintf(wp.p[e][r] / sc);       // round-half-even, matches jnp.round
    t = fminf(1.f, fmaxf(-1.f, t));
    g_wq[(size_t)e * WELEM + ((size_t)(k * C_ + o) * C_ + i)] = __float2half_rn(t);
}

// ---------------- transpose x[b][C][L] fp32 -> xT[b][L][C] fp16 ---------------
__global__ void tr_kernel(const float* __restrict__ x) {
    __shared__ __half t[32][33];
    int b  = blockIdx.z;
    int l0 = blockIdx.x * 32, c0 = blockIdx.y * 32;
    int tx = threadIdx.x, ty = threadIdx.y;   // 32 x 8
    const float* xp = x + ((size_t)b * C_ + c0) * L_ + l0;
#pragma unroll
    for (int j = 0; j < 32; j += 8)
        t[ty + j][tx] = __float2half_rn(xp[(size_t)(ty + j) * L_ + tx]);
    __syncthreads();
    __half* xo = g_xt0 + ((size_t)b * L_ + l0) * C_ + c0;
#pragma unroll
    for (int j = 0; j < 32; j += 8)
        xo[(size_t)(ty + j) * C_ + tx] = t[tx][ty + j];
}

// ---------------- fused conv (mma.sync fp16, ldmatrix + cp.async 2-buf) -------
// CTA tile: 128 o x 128 n. K = 3 taps x 512 ic in 16 chunks of 32.
// Dynamic smem, rows padded to 40 halves (80B): ldmatrix phases conflict-free.
//   Ws: [buf][3][128][40]  at offset buf*30720          (2 x 30720 B)
//   Xs: [buf][144][40]     at offset 61440 + buf*11520  (2 x 11520 B)
// Total 84480 B dynamic.
// B operand: Xs stored [n][k] (k contiguous) -> NON-trans ldmatrix gives the
// exact m16n8k16 B fragment (thread i: Xs[n=i>>2][k=(i&3)*2 .. +1]).
// MODE 0: out_h[L][C] = fp16(leaky(scale*acc + bias))
// MODE 1: r = prev_f + scale*acc + bias -> out_f [C][L] fp32; opt out_h [L][C]
#define CONV_SMEM 84480
template<int D, int MODE>
__global__ __launch_bounds__(256, 2)
void conv_kernel(const __half* __restrict__ xin,        // [b][L][C] fp16
                 const __half* __restrict__ wq,         // [3][512][512] ternary fp16
                 const float* __restrict__ scale_p,
                 const float* __restrict__ bias,
                 const float* __restrict__ prev_f,
                 float* __restrict__ out_f,
                 __half* __restrict__ out_h,
                 int write_h)
{
    extern __shared__ char dsm[];
    const uint32_t sb = smem_u32(dsm);

    const int n0 = blockIdx.x * 128;
    const int o0 = blockIdx.y * 128;
    const int b  = blockIdx.z;
    const int tid  = threadIdx.x;
    const int lane = tid & 31;
    const int wid  = tid >> 5;
    const int oW = (wid & 3) * 32;   // warp o-offset
    const int nW = (wid >> 2) * 64;  // warp n-offset

    float acc[2][8][4];
#pragma unroll
    for (int a = 0; a < 2; a++)
#pragma unroll
        for (int c = 0; c < 8; c++)
#pragma unroll
            for (int j = 0; j < 4; j++) acc[a][c][j] = 0.f;

    const size_t bL = (size_t)b * L_;

    // stage fill: 1536 W chunks (3*128 rows x 4x16B) + 576 X chunks (144 x 4x16B)
    auto fill = [&](int s, int buf) {
        int ic = s * 32;
        uint32_t wbase = sb + buf * 30720;
        uint32_t xbase = sb + 61440 + buf * 11520;
#pragma unroll
        for (int i = 0; i < 9; i++) {
            int c = tid + i * 256;
            if (c < 1536) {                       // weights
                int row = c >> 2, q = c & 3;
                int t = row >> 7, o = row & 127;
                const __half* src = wq + ((size_t)(t * C_ + o0 + o)) * C_ + ic + q * 8;
                cpa16(wbase + (uint32_t)(((t * 128 + o) * 40 + q * 8) * 2), src, 16);
            } else if (c < 2112) {                // activations
                int c2 = c - 1536;
                int r = c2 >> 2, q = c2 & 3;
                int l = n0 - 8 + r;
                int lc = l < 0 ? 0 : (l >= L_ ? L_ - 1 : l);
                uint32_t sz = (l >= 0 && l < L_) ? 16u : 0u;
                const __half* src = xin + (bL + lc) * C_ + ic + q * 8;
                cpa16(xbase + (uint32_t)((r * 40 + q * 8) * 2), src, sz);
            }
        }
        asm volatile("cp.async.commit_group;" ::: "memory");
    };

    // per-lane ldmatrix address components
    const uint32_t aRow  = lane & 15;                 // A: row within 16
    const uint32_t aColH = (lane >> 4) * 8;           // A: k-half select
    const uint32_t bR    = lane & 7;                  // B: n-row within 8x8 tile
    const uint32_t bNH   = ((lane >> 4) & 1) * 8;     // B: n-tile select (matrices 2,3)
    const uint32_t bKH   = ((lane >> 3) & 1) * 8;     // B: k-half select (matrices 1,3)

    fill(0, 0);
    for (int s = 0; s < 16; s++) {
        const int buf = s & 1;
        asm volatile("cp.async.wait_group 0;" ::: "memory");
        __syncthreads();
        if (s + 1 < 16) fill(s + 1, buf ^ 1);

        const uint32_t wbase = sb + buf * 30720;
        const uint32_t xbase = sb + 61440 + buf * 11520;

#pragma unroll
        for (int t = 0; t < 3; t++) {
            const int shift = (8 - D) + t * D;
            const uint32_t nrow = nW + bNH + bR + shift;
#pragma unroll
            for (int kg = 0; kg < 2; kg++) {
                uint32_t a0,a1,a2,a3, a4,a5,a6,a7;
                uint32_t aa = wbase + ((t * 128 + oW + aRow) * 40 + kg * 16 + aColH) * 2;
                LDSM_X4(a0,a1,a2,a3, aa);
                LDSM_X4(a4,a5,a6,a7, aa + 16 * 80);
#pragma unroll
                for (int nia = 0; nia < 4; nia++) {
                    uint32_t b0,b1,b2,b3;
                    uint32_t ba = xbase + ((nrow + nia * 16) * 40 + kg * 16 + bKH) * 2;
                    LDSM_X4(b0,b1,b2,b3, ba);     // non-trans: [n][k] rows ARE B frags
                    MMA16816(acc[0][2*nia    ], a0,a1,a2,a3, b0,b1);
                    MMA16816(acc[0][2*nia + 1], a0,a1,a2,a3, b2,b3);
                    MMA16816(acc[1][2*nia    ], a4,a5,a6,a7, b0,b1);
                    MMA16816(acc[1][2*nia + 1], a4,a5,a6,a7, b2,b3);
                }
            }
        }
    }

    const float scale = *scale_p;
#pragma unroll
    for (int mi = 0; mi < 2; mi++) {
#pragma unroll
        for (int half = 0; half < 2; half++) {
            int o = o0 + oW + mi*16 + (lane >> 2) + half*8;
            float bv = bias[o];
#pragma unroll
            for (int ni = 0; ni < 8; ni++) {
                int c = n0 + nW + ni*8 + (lane & 3)*2;
                float v0 = acc[mi][ni][half*2 + 0] * scale + bv;
                float v1 = acc[mi][ni][half*2 + 1] * scale + bv;
                if (MODE == 0) {
                    v0 = v0 >= 0.f ? v0 : 0.1f * v0;
                    v1 = v1 >= 0.f ? v1 : 0.1f * v1;
                    out_h[(bL + c    ) * C_ + o] = __float2half_rn(v0);
                    out_h[(bL + c + 1) * C_ + o] = __float2half_rn(v1);
                } else {
                    size_t gi = ((size_t)b * C_ + o) * L_ + c;
                    float2 pv = *((const float2*)(prev_f + gi));
                    float r0 = pv.x + v0, r1 = pv.y + v1;
                    *((float2*)(out_f + gi)) = make_float2(r0, r1);
                    if (write_h) {
                        out_h[(bL + c    ) * C_ + o] = __float2half_rn(r0);
                        out_h[(bL + c + 1) * C_ + o] = __float2half_rn(r1);
                    }
                }
            }
        }
    }
}

// ---------------- launch ------------------------------------------------------
extern "C" void kernel_launch(void* const* d_in, const int* in_sizes, int n_in,
                              void* d_out, int out_size)
{
    (void)in_sizes; (void)n_in; (void)out_size;
    const float* x = (const float*)d_in[0];
    WPtrs wp;
    const float* biasA[3];
    const float* biasB[3];
    for (int br = 0; br < 3; br++) {
        wp.p[2*br + 0] = (const float*)d_in[1 + 4*br];   // wA
        biasA[br]      = (const float*)d_in[2 + 4*br];   // bA
        wp.p[2*br + 1] = (const float*)d_in[3 + 4*br];   // wB
        biasB[br]      = (const float*)d_in[4 + 4*br];   // bB
    }

    void *p_wq, *p_x0, *p_x1, *p_y, *p_f0, *p_f1, *p_sc;
    cudaGetSymbolAddress(&p_wq, g_wq);
    cudaGetSymbolAddress(&p_x0, g_xt0);
    cudaGetSymbolAddress(&p_x1, g_xt1);
    cudaGetSymbolAddress(&p_y,  g_yt);
    cudaGetSymbolAddress(&p_f0, g_xf0);
    cudaGetSymbolAddress(&p_f1, g_xf1);
    cudaGetSymbolAddress(&p_sc, g_scales);
    __half* wq  = (__half*)p_wq;
    __half* xt0 = (__half*)p_x0;
    __half* xt1 = (__half*)p_x1;
    __half* yt  = (__half*)p_y;
    float* xf0 = (float*)p_f0;
    float* xf1 = (float*)p_f1;
    float* scales = (float*)p_sc;

    cudaFuncSetAttribute(conv_kernel<1,0>, cudaFuncAttributeMaxDynamicSharedMemorySize, CONV_SMEM);
    cudaFuncSetAttribute(conv_kernel<1,1>, cudaFuncAttributeMaxDynamicSharedMemorySize, CONV_SMEM);
    cudaFuncSetAttribute(conv_kernel<3,0>, cudaFuncAttributeMaxDynamicSharedMemorySize, CONV_SMEM);
    cudaFuncSetAttribute(conv_kernel<5,0>, cudaFuncAttributeMaxDynamicSharedMemorySize, CONV_SMEM);

    dim3 rg(96, NW);
    wabs_kernel<<<rg, 256>>>(wp);
    finalize_kernel<<<1, 32>>>();
    quant_kernel<<<(NW * WELEM + 255) / 256, 256>>>(wp);
    dim3 tg(L_ / 32, C_ / 32, B_);
    tr_kernel<<<tg, dim3(32, 8)>>>(x);

    dim3 cg(L_ / 128, C_ / 128, B_);   // 64 x 4 x 8 = 2048 CTAs
    // branch 0: dilation 1
    conv_kernel<1, 0><<<cg, 256, CONV_SMEM>>>(xt0, wq + 0*(size_t)WELEM, scales + 0, biasA[0],
                                              nullptr, nullptr, yt, 0);
    conv_kernel<1, 1><<<cg, 256, CONV_SMEM>>>(yt,  wq + 1*(size_t)WELEM, scales + 1, biasB[0],
                                              x, xf0, xt1, 1);
    // branch 1: dilation 3
    conv_kernel<3, 0><<<cg, 256, CONV_SMEM>>>(xt1, wq + 2*(size_t)WELEM, scales + 2, biasA[1],
                                              nullptr, nullptr, yt, 0);
    conv_kernel<1, 1><<<cg, 256, CONV_SMEM>>>(yt,  wq + 3*(size_t)WELEM, scales + 3, biasB[1],
                                              xf0, xf1, xt0, 1);
    // branch 2: dilation 5
    conv_kernel<5, 0><<<cg, 256, CONV_SMEM>>>(xt0, wq + 4*(size_t)WELEM, scales + 4, biasA[2],
                                              nullptr, nullptr, yt, 0);
    conv_kernel<1, 1><<<cg, 256, CONV_SMEM>>>(yt,  wq + 5*(size_t)WELEM, scales + 5, biasB[2],
                                              xf1, (float*)d_out, nullptr, 0);
}

// round 13
// speedup vs baseline: 2.7353x; 1.0313x over previous
#include <cuda_runtime.h>
#include <cuda_fp16.h>
#include <cstdint>
#include <cstddef>

#define B_   8
#define C_   512
#define L_   8192
#define NW   6
#define WELEM (512*512*3)
#define ACT  (B_*C_*L_)   // 33554432

// ---------------- scratch (device globals; no allocs allowed) ----------------
__device__ __align__(256) double  g_partial[NW*96];
__device__ __align__(256) float   g_scales[NW];
__device__ __align__(256) __half  g_wq[NW*WELEM];   // per weight: [k][o][i] ternary fp16
__device__ __align__(256) __half  g_xt0[ACT];       // fp16 activations [b][L][C] ping
__device__ __align__(256) __half  g_xt1[ACT];       // pong
__device__ __align__(256) __half  g_yt[ACT];        // branch intermediate [b][L][C]
__device__ __align__(256) float   g_xf0[ACT];       // fp32 residual [b][C][L] ping
__device__ __align__(256) float   g_xf1[ACT];       // pong

struct WPtrs { const float* p[NW]; };

__device__ __forceinline__ uint32_t smem_u32(const void* p) {
    uint32_t a;
    asm("{ .reg .u64 t; cvta.to.shared.u64 t, %1; cvt.u32.u64 %0, t; }"
        : "=r"(a) : "l"(p));
    return a;
}
__device__ __forceinline__ void cpa16(uint32_t dst, const void* src, uint32_t ssize) {
    asm volatile("cp.async.cg.shared.global [%0], [%1], 16, %2;"
                 :: "r"(dst), "l"(src), "r"(ssize) : "memory");
}
#define LDSM_X4(r0,r1,r2,r3,a) \
    asm volatile("ldmatrix.sync.aligned.m8n8.x4.shared.b16 {%0,%1,%2,%3}, [%4];" \
                 : "=r"(r0),"=r"(r1),"=r"(r2),"=r"(r3) : "r"(a))
#define MMA16816(acc, A0,A1,A2,A3, B0,B1) \
    asm volatile( \
        "mma.sync.aligned.m16n8k16.row.col.f32.f16.f16.f32 " \
        "{%0,%1,%2,%3}, {%4,%5,%6,%7}, {%8,%9}, {%0,%1,%2,%3};\n" \
        : "+f"((acc)[0]), "+f"((acc)[1]), "+f"((acc)[2]), "+f"((acc)[3]) \
        : "r"(A0), "r"(A1), "r"(A2), "r"(A3), "r"(B0), "r"(B1))

// ---------------- pass 1: deterministic |w| partial sums (double) ------------
__global__ void wabs_kernel(WPtrs wp) {
    int e = blockIdx.y;
    int chunk = blockIdx.x;                 // 96 chunks of 8192
    const float* w = wp.p[e] + chunk * 8192;
    double s = 0.0;
    for (int i = threadIdx.x; i < 8192; i += 256) s += (double)fabsf(w[i]);
    __shared__ double sm[256];
    sm[threadIdx.x] = s;
    __syncthreads();
    for (int off = 128; off > 0; off >>= 1) {
        if (threadIdx.x < off) sm[threadIdx.x] += sm[threadIdx.x + off];
        __syncthreads();
    }
    if (threadIdx.x == 0) g_partial[e*96 + chunk] = sm[0];
}

// ---------------- pass 2: finalize scales ------------------------------------
__global__ void finalize_kernel() {
    int e = threadIdx.x;
    if (e < NW) {
        double s = 0.0;
        for (int i = 0; i < 96; i++) s += g_partial[e*96 + i];
        g_scales[e] = (float)(s / (double)WELEM) + 1e-5f;
    }
}

// ---------------- pass 3: ternary quantize + rearrange [o][i][k]->[k][o][i] --
__global__ void quant_kernel(WPtrs wp) {
    int idx = blockIdx.x * 256 + threadIdx.x;
    if (idx >= NW * WELEM) return;
    int e = idx / WELEM;
    int r = idx - e * WELEM;
    int o = r / 1536;
    int rem = r - o * 1536;
    int i = rem / 3;
    int k = rem - i * 3;
    float sc = g_scales[e];
    float t = rintf(wp.p[e][r] / sc);       // round-half-even, matches jnp.round
    t = fminf(1.f, fmaxf(-1.f, t));
    g_wq[(size_t)e * WELEM + ((size_t)(k * C_ + o) * C_ + i)] = __float2half_rn(t);
}

// ---------------- transpose x[b][C][L] fp32 -> xT[b][L][C] fp16 ---------------
// 32 l x 64 c tiles; half2 stores give 128B/warp write transactions.
__global__ void tr_kernel(const float* __restrict__ x) {
    __shared__ __half t[64][33];   // [c][l]
    int b  = blockIdx.z;
    int l0 = blockIdx.x * 32, c0 = blockIdx.y * 64;
    int tx = threadIdx.x, ty = threadIdx.y;   // 32 x 8
    const float* xp = x + ((size_t)b * C_ + c0) * L_ + l0;
#pragma unroll
    for (int j = 0; j < 64; j += 8)
        t[ty + j][tx] = __float2half_rn(xp[(size_t)(ty + j) * L_ + tx]);
    __syncthreads();
    __half* xo = g_xt0 + ((size_t)b * L_ + l0) * C_ + c0;
#pragma unroll
    for (int r = 0; r < 4; r++) {
        int l = ty * 4 + r;                   // uniform per warp
        __half2 v;
        v.x = t[2 * tx    ][l];
        v.y = t[2 * tx + 1][l];
        *(__half2*)(xo + (size_t)l * C_ + 2 * tx) = v;
    }
}

// ---------------- fused conv (mma.sync fp16, ldmatrix + cp.async 2-buf) -------
// CTA tile: 128 o x 128 n. K = 3 taps x 512 ic in 16 chunks of 32.
// Dynamic smem, rows padded to 40 halves (80B): ldmatrix phases conflict-free.
//   Ws: [buf][3][128][40]  at offset buf*30720          (2 x 30720 B)
//   Xs: [buf][144][40]     at offset 61440 + buf*11520  (2 x 11520 B)
// Total 84480 B dynamic. Epilogue reuses smem as 128n x 136o fp16 staging tile
// (34816 B) for fully-coalesced [L][C] fp16 stores.
// B operand: Xs stored [n][k] (k contiguous) -> NON-trans ldmatrix gives the
// exact m16n8k16 B fragment (thread i: Xs[n=i>>2][k=(i&3)*2 .. +1]).
// MODE 0: out_h[L][C] = fp16(leaky(scale*acc + bias))
// MODE 1: r = prev_f + scale*acc + bias -> out_f [C][L] fp32; opt out_h [L][C]
#define CONV_SMEM 84480
template<int D, int MODE>
__global__ __launch_bounds__(256, 2)
void conv_kernel(const __half* __restrict__ xin,        // [b][L][C] fp16
                 const __half* __restrict__ wq,         // [3][512][512] ternary fp16
                 const float* __restrict__ scale_p,
                 const float* __restrict__ bias,
                 const float* __restrict__ prev_f,
                 float* __restrict__ out_f,
                 __half* __restrict__ out_h,
                 int write_h)
{
    extern __shared__ char dsm[];
    const uint32_t sb = smem_u32(dsm);

    const int n0 = blockIdx.x * 128;
    const int o0 = blockIdx.y * 128;
    const int b  = blockIdx.z;
    const int tid  = threadIdx.x;
    const int lane = tid & 31;
    const int wid  = tid >> 5;
    const int oW = (wid & 3) * 32;   // warp o-offset
    const int nW = (wid >> 2) * 64;  // warp n-offset

    float acc[2][8][4];
#pragma unroll
    for (int a = 0; a < 2; a++)
#pragma unroll
        for (int c = 0; c < 8; c++)
#pragma unroll
            for (int j = 0; j < 4; j++) acc[a][c][j] = 0.f;

    const size_t bL = (size_t)b * L_;

    // stage fill: 1536 W chunks (3*128 rows x 4x16B) + 576 X chunks (144 x 4x16B)
    auto fill = [&](int s, int buf) {
        int ic = s * 32;
        uint32_t wbase = sb + buf * 30720;
        uint32_t xbase = sb + 61440 + buf * 11520;
#pragma unroll
        for (int i = 0; i < 9; i++) {
            int c = tid + i * 256;
            if (c < 1536) {                       // weights
                int row = c >> 2, q = c & 3;
                int t = row >> 7, o = row & 127;
                const __half* src = wq + ((size_t)(t * C_ + o0 + o)) * C_ + ic + q * 8;
                cpa16(wbase + (uint32_t)(((t * 128 + o) * 40 + q * 8) * 2), src, 16);
            } else if (c < 2112) {                // activations
                int c2 = c - 1536;
                int r = c2 >> 2, q = c2 & 3;
                int l = n0 - 8 + r;
                int lc = l < 0 ? 0 : (l >= L_ ? L_ - 1 : l);
                uint32_t sz = (l >= 0 && l < L_) ? 16u : 0u;
                const __half* src = xin + (bL + lc) * C_ + ic + q * 8;
                cpa16(xbase + (uint32_t)((r * 40 + q * 8) * 2), src, sz);
            }
        }
        asm volatile("cp.async.commit_group;" ::: "memory");
    };

    // per-lane ldmatrix address components
    const uint32_t aRow  = lane & 15;                 // A: row within 16
    const uint32_t aColH = (lane >> 4) * 8;           // A: k-half select
    const uint32_t bR    = lane & 7;                  // B: n-row within 8x8 tile
    const uint32_t bNH   = ((lane >> 4) & 1) * 8;     // B: n-tile select (matrices 2,3)
    const uint32_t bKH   = ((lane >> 3) & 1) * 8;     // B: k-half select (matrices 1,3)

    fill(0, 0);
    for (int s = 0; s < 16; s++) {
        const int buf = s & 1;
        asm volatile("cp.async.wait_group 0;" ::: "memory");
        __syncthreads();
        if (s + 1 < 16) fill(s + 1, buf ^ 1);

        const uint32_t wbase = sb + buf * 30720;
        const uint32_t xbase = sb + 61440 + buf * 11520;

#pragma unroll
        for (int t = 0; t < 3; t++) {
            const int shift = (8 - D) + t * D;
            const uint32_t nrow = nW + bNH + bR + shift;
#pragma unroll
            for (int kg = 0; kg < 2; kg++) {
                uint32_t a0,a1,a2,a3, a4,a5,a6,a7;
                uint32_t aa = wbase + ((t * 128 + oW + aRow) * 40 + kg * 16 + aColH) * 2;
                LDSM_X4(a0,a1,a2,a3, aa);
                LDSM_X4(a4,a5,a6,a7, aa + 16 * 80);
#pragma unroll
                for (int nia = 0; nia < 4; nia++) {
                    uint32_t b0,b1,b2,b3;
                    uint32_t ba = xbase + ((nrow + nia * 16) * 40 + kg * 16 + bKH) * 2;
                    LDSM_X4(b0,b1,b2,b3, ba);     // non-trans: [n][k] rows ARE B frags
                    MMA16816(acc[0][2*nia    ], a0,a1,a2,a3, b0,b1);
                    MMA16816(acc[0][2*nia + 1], a0,a1,a2,a3, b2,b3);
                    MMA16816(acc[1][2*nia    ], a4,a5,a6,a7, b0,b1);
                    MMA16816(acc[1][2*nia + 1], a4,a5,a6,a7, b2,b3);
                }
            }
        }
    }

    const float scale = *scale_p;
    const bool stage_h = (MODE == 0) || (write_h != 0);
    __half* ho = (__half*)dsm;               // 128 rows x 136 halves (272 B/row)

    if (stage_h) __syncthreads();            // all K-loop smem readers done

#pragma unroll
    for (int mi = 0; mi < 2; mi++) {
#pragma unroll
        for (int half = 0; half < 2; half++) {
            int ol = oW + mi*16 + (lane >> 2) + half*8;   // 0..127
            int o  = o0 + ol;
            float bv = bias[o];
#pragma unroll
            for (int ni = 0; ni < 8; ni++) {
                int cl = nW + ni*8 + (lane & 3)*2;        // 0..127
                float v0 = acc[mi][ni][half*2 + 0] * scale + bv;
                float v1 = acc[mi][ni][half*2 + 1] * scale + bv;
                if (MODE == 0) {
                    v0 = v0 >= 0.f ? v0 : 0.1f * v0;
                    v1 = v1 >= 0.f ? v1 : 0.1f * v1;
                    ho[(cl    ) * 136 + ol] = __float2half_rn(v0);
                    ho[(cl + 1) * 136 + ol] = __float2half_rn(v1);
                } else {
                    size_t gi = ((size_t)b * C_ + o) * L_ + n0 + cl;
                    float2 pv = *((const float2*)(prev_f + gi));
                    float r0 = pv.x + v0, r1 = pv.y + v1;
                    *((float2*)(out_f + gi)) = make_float2(r0, r1);
                    if (write_h) {
                        ho[(cl    ) * 136 + ol] = __float2half_rn(r0);
                        ho[(cl + 1) * 136 + ol] = __float2half_rn(r1);
                    }
                }
            }
        }
    }

    if (stage_h) {
        __syncthreads();
        // cooperative coalesced write: 128 rows x 256 B
#pragma unroll
        for (int i = 0; i < 8; i++) {
            int idx = i * 256 + tid;          // 0..2047
            int row = idx >> 4, seg = idx & 15;
            uint4 v = *(const uint4*)(dsm + row * 272 + seg * 16);
            *(uint4*)(out_h + (bL + n0 + row) * C_ + o0 + seg * 8) = v;
        }
    }
}

// ---------------- launch ------------------------------------------------------
extern "C" void kernel_launch(void* const* d_in, const int* in_sizes, int n_in,
                              void* d_out, int out_size)
{
    (void)in_sizes; (void)n_in; (void)out_size;
    const float* x = (const float*)d_in[0];
    WPtrs wp;
    const float* biasA[3];
    const float* biasB[3];
    for (int br = 0; br < 3; br++) {
        wp.p[2*br + 0] = (const float*)d_in[1 + 4*br];   // wA
        biasA[br]      = (const float*)d_in[2 + 4*br];   // bA
        wp.p[2*br + 1] = (const float*)d_in[3 + 4*br];   // wB
        biasB[br]      = (const float*)d_in[4 + 4*br];   // bB
    }

    void *p_wq, *p_x0, *p_x1, *p_y, *p_f0, *p_f1, *p_sc;
    cudaGetSymbolAddress(&p_wq, g_wq);
    cudaGetSymbolAddress(&p_x0, g_xt0);
    cudaGetSymbolAddress(&p_x1, g_xt1);
    cudaGetSymbolAddress(&p_y,  g_yt);
    cudaGetSymbolAddress(&p_f0, g_xf0);
    cudaGetSymbolAddress(&p_f1, g_xf1);
    cudaGetSymbolAddress(&p_sc, g_scales);
    __half* wq  = (__half*)p_wq;
    __half* xt0 = (__half*)p_x0;
    __half* xt1 = (__half*)p_x1;
    __half* yt  = (__half*)p_y;
    float* xf0 = (float*)p_f0;
    float* xf1 = (float*)p_f1;
    float* scales = (float*)p_sc;

    cudaFuncSetAttribute(conv_kernel<1,0>, cudaFuncAttributeMaxDynamicSharedMemorySize, CONV_SMEM);
    cudaFuncSetAttribute(conv_kernel<1,1>, cudaFuncAttributeMaxDynamicSharedMemorySize, CONV_SMEM);
    cudaFuncSetAttribute(conv_kernel<3,0>, cudaFuncAttributeMaxDynamicSharedMemorySize, CONV_SMEM);
    cudaFuncSetAttribute(conv_kernel<5,0>, cudaFuncAttributeMaxDynamicSharedMemorySize, CONV_SMEM);

    dim3 rg(96, NW);
    wabs_kernel<<<rg, 256>>>(wp);
    finalize_kernel<<<1, 32>>>();
    quant_kernel<<<(NW * WELEM + 255) / 256, 256>>>(wp);
    dim3 tg(L_ / 32, C_ / 64, B_);
    tr_kernel<<<tg, dim3(32, 8)>>>(x);

    dim3 cg(L_ / 128, C_ / 128, B_);   // 64 x 4 x 8 = 2048 CTAs
    // branch 0: dilation 1
    conv_kernel<1, 0><<<cg, 256, CONV_SMEM>>>(xt0, wq + 0*(size_t)WELEM, scales + 0, biasA[0],
                                              nullptr, nullptr, yt, 0);
    conv_kernel<1, 1><<<cg, 256, CONV_SMEM>>>(yt,  wq + 1*(size_t)WELEM, scales + 1, biasB[0],
                                              x, xf0, xt1, 1);
    // branch 1: dilation 3
    conv_kernel<3, 0><<<cg, 256, CONV_SMEM>>>(xt1, wq + 2*(size_t)WELEM, scales + 2, biasA[1],
                                              nullptr, nullptr, yt, 0);
    conv_kernel<1, 1><<<cg, 256, CONV_SMEM>>>(yt,  wq + 3*(size_t)WELEM, scales + 3, biasB[1],
                                              xf0, xf1, xt0, 1);
    // branch 2: dilation 5
    conv_kernel<5, 0><<<cg, 256, CONV_SMEM>>>(xt0, wq + 4*(size_t)WELEM, scales + 4, biasA[2],
                                              nullptr, nullptr, yt, 0);
    conv_kernel<1, 1><<<cg, 256, CONV_SMEM>>>(yt,  wq + 5*(size_t)WELEM, scales + 5, biasB[2],
                                              xf1, (float*)d_out, nullptr, 0);
}